// round 1
// baseline (speedup 1.0000x reference)
#include <cuda_runtime.h>
#include <math.h>

#define BB 8
#define SS 2048
#define DD 768
#define HH 12
#define HD 64
#define M_ROWS (BB*SS)

// Scratch (allocation-free: __device__ globals). ~201 MB total.
__device__ float g_Q[BB*HH*SS*HD];
__device__ float g_K[BB*HH*SS*HD];
__device__ float g_V[BB*HH*SS*HD];
__device__ float g_C[BB*SS*DD];

// ---------------------------------------------------------------------------
// Kernel 1: fused QKV projection.
// Grid: x = 36 tiles (mat*12 + head), y = 256 M-tiles (64 rows each).
// One 64-wide N tile == exactly one head's [D, 64] weight block (contiguous).
// Writes Q/K/V in [B,H,S,HD] layout.
// ---------------------------------------------------------------------------
__global__ __launch_bounds__(256)
void qkv_kernel(const float* __restrict__ x,
                const float* __restrict__ Wq, const float* __restrict__ bq,
                const float* __restrict__ Wk, const float* __restrict__ bk,
                const float* __restrict__ Wv, const float* __restrict__ bv) {
    int nt  = blockIdx.x;
    int mat = nt / HH;          // 0=Q, 1=K, 2=V
    int h   = nt % HH;
    const float* W    = (mat == 0) ? Wq : (mat == 1) ? Wk : Wv;
    const float* bias = (mat == 0) ? bq : (mat == 1) ? bk : bv;
    float*       Out  = (mat == 0) ? g_Q : (mat == 1) ? g_K : g_V;
    W    += h * DD * HD;
    bias += h * HD;

    int m0  = blockIdx.y * 64;
    int tid = threadIdx.x;
    int tx  = tid & 15, ty = tid >> 4;

    __shared__ float As[16][64];   // transposed A tile: As[k][row]
    __shared__ float Bs[16][64];   // Bs[k][col]

    float acc[4][4] = {};

    int a_row = tid >> 2;          // 0..63
    int a_kv  = (tid & 3) * 4;     // 0,4,8,12
    int b_row = tid >> 4;          // 0..15
    int b_cv  = (tid & 15) * 4;    // 0..60

    for (int k0 = 0; k0 < DD; k0 += 16) {
        float4 av = *(const float4*)&x[(m0 + a_row) * DD + k0 + a_kv];
        As[a_kv + 0][a_row] = av.x;
        As[a_kv + 1][a_row] = av.y;
        As[a_kv + 2][a_row] = av.z;
        As[a_kv + 3][a_row] = av.w;
        *(float4*)&Bs[b_row][b_cv] = *(const float4*)&W[(k0 + b_row) * HD + b_cv];
        __syncthreads();
        #pragma unroll
        for (int k = 0; k < 16; k++) {
            float4 a = *(float4*)&As[k][ty * 4];
            float4 b = *(float4*)&Bs[k][tx * 4];
            float ar[4] = {a.x, a.y, a.z, a.w};
            float br[4] = {b.x, b.y, b.z, b.w};
            #pragma unroll
            for (int i = 0; i < 4; i++)
                #pragma unroll
                for (int j = 0; j < 4; j++)
                    acc[i][j] += ar[i] * br[j];
        }
        __syncthreads();
    }

    int b_idx  = m0 / SS;          // whole tile within one batch (SS % 64 == 0)
    int s_base = m0 % SS;
    float4 b4 = *(const float4*)&bias[tx * 4];
    #pragma unroll
    for (int i = 0; i < 4; i++) {
        int s = s_base + ty * 4 + i;
        float4 o;
        o.x = acc[i][0] + b4.x;
        o.y = acc[i][1] + b4.y;
        o.z = acc[i][2] + b4.z;
        o.w = acc[i][3] + b4.w;
        *(float4*)&Out[(((size_t)b_idx * HH + h) * SS + s) * HD + tx * 4] = o;
    }
}

// ---------------------------------------------------------------------------
// Kernel 2: flash attention (online softmax), BR=BC=64.
// Grid: x = 32 q-tiles, y = 96 (b*H+h). 256 threads, 4x4 microtile.
// Writes ctx directly in [B, S, H*HD] layout (epilogue becomes a plain GEMM).
// ---------------------------------------------------------------------------
__global__ __launch_bounds__(256)
void attn_kernel() {
    int bh = blockIdx.y;
    int qt = blockIdx.x;
    const float* Qg = g_Q + (size_t)bh * SS * HD;
    const float* Kg = g_K + (size_t)bh * SS * HD;
    const float* Vg = g_V + (size_t)bh * SS * HD;
    int b = bh / HH, h = bh % HH;

    extern __shared__ float sm[];
    float* Qs = sm;                // [e][r]  64*64
    float* Ks = Qs + 64 * 64;      // [e][c]  64*64
    float* Vs = Ks + 64 * 64;      // [c][e]  64*64
    float* Ps = Vs + 64 * 64;      // [r][c]  64*65 (padded vs 16-way conflicts)

    int tid = threadIdx.x;
    int tx  = tid & 15, ty = tid >> 4;
    int q0  = qt * 64;

    // Load Q tile transposed: Qs[e][r]
    #pragma unroll
    for (int it = 0; it < 4; it++) {
        int idx = tid + it * 256;
        int r   = idx >> 4;
        int ev  = (idx & 15) * 4;
        float4 v = *(const float4*)&Qg[(q0 + r) * HD + ev];
        Qs[(ev + 0) * 64 + r] = v.x;
        Qs[(ev + 1) * 64 + r] = v.y;
        Qs[(ev + 2) * 64 + r] = v.z;
        Qs[(ev + 3) * 64 + r] = v.w;
    }

    float m_i[4], l_i[4], acc[4][4];
    #pragma unroll
    for (int i = 0; i < 4; i++) {
        m_i[i] = -1e30f; l_i[i] = 0.f;
        #pragma unroll
        for (int j = 0; j < 4; j++) acc[i][j] = 0.f;
    }

    const float inv_scale = 1.0f / (8.0f + 1e-6f);   // 1/(sqrt(64)+EPS)

    for (int kc0 = 0; kc0 < SS; kc0 += 64) {
        __syncthreads();  // protect Ks/Vs/Ps (and first-iter Qs) readers
        // Load K chunk transposed (Ks[e][c]) and V chunk direct (Vs[c][e]).
        #pragma unroll
        for (int it = 0; it < 4; it++) {
            int idx = tid + it * 256;
            int c   = idx >> 4;
            int ev  = (idx & 15) * 4;
            float4 kv = *(const float4*)&Kg[(kc0 + c) * HD + ev];
            Ks[(ev + 0) * 64 + c] = kv.x;
            Ks[(ev + 1) * 64 + c] = kv.y;
            Ks[(ev + 2) * 64 + c] = kv.z;
            Ks[(ev + 3) * 64 + c] = kv.w;
            *(float4*)&Vs[c * 64 + ev] = *(const float4*)&Vg[(kc0 + c) * HD + ev];
        }
        __syncthreads();

        // Scores: sc[i][j] = sum_e Q[r0+i][e] * K[c0+j][e]
        float sc[4][4] = {};
        #pragma unroll
        for (int e = 0; e < 64; e++) {
            float4 qa = *(float4*)&Qs[e * 64 + ty * 4];
            float4 kb = *(float4*)&Ks[e * 64 + tx * 4];
            float qr[4] = {qa.x, qa.y, qa.z, qa.w};
            float kr[4] = {kb.x, kb.y, kb.z, kb.w};
            #pragma unroll
            for (int i = 0; i < 4; i++)
                #pragma unroll
                for (int j = 0; j < 4; j++)
                    sc[i][j] += qr[i] * kr[j];
        }

        // Online softmax per row (16 threads along tx share a row; width-16 shuffles)
        #pragma unroll
        for (int i = 0; i < 4; i++) {
            float s0 = sc[i][0] * inv_scale;
            float s1 = sc[i][1] * inv_scale;
            float s2 = sc[i][2] * inv_scale;
            float s3 = sc[i][3] * inv_scale;
            float rm = fmaxf(fmaxf(s0, s1), fmaxf(s2, s3));
            #pragma unroll
            for (int o = 8; o >= 1; o >>= 1)
                rm = fmaxf(rm, __shfl_xor_sync(0xffffffffu, rm, o, 16));
            float m_new = fmaxf(m_i[i], rm);
            float fac   = __expf(m_i[i] - m_new);
            float p0 = __expf(s0 - m_new);
            float p1 = __expf(s1 - m_new);
            float p2 = __expf(s2 - m_new);
            float p3 = __expf(s3 - m_new);
            float rs = p0 + p1 + p2 + p3;
            #pragma unroll
            for (int o = 8; o >= 1; o >>= 1)
                rs += __shfl_xor_sync(0xffffffffu, rs, o, 16);
            l_i[i] = l_i[i] * fac + rs;
            m_i[i] = m_new;
            #pragma unroll
            for (int j = 0; j < 4; j++) acc[i][j] *= fac;
            int r = ty * 4 + i;
            Ps[r * 65 + tx * 4 + 0] = p0;
            Ps[r * 65 + tx * 4 + 1] = p1;
            Ps[r * 65 + tx * 4 + 2] = p2;
            Ps[r * 65 + tx * 4 + 3] = p3;
        }
        __syncthreads();

        // O += P @ V  (output cols = tx*4..tx*4+3 over HD)
        #pragma unroll 8
        for (int c = 0; c < 64; c++) {
            float4 v = *(float4*)&Vs[c * 64 + tx * 4];
            #pragma unroll
            for (int i = 0; i < 4; i++) {
                float p = Ps[(ty * 4 + i) * 65 + c];
                acc[i][0] += p * v.x;
                acc[i][1] += p * v.y;
                acc[i][2] += p * v.z;
                acc[i][3] += p * v.w;
            }
        }
    }

    // Final normalize and store ctx in [B, S, H*HD]
    #pragma unroll
    for (int i = 0; i < 4; i++) {
        float inv_l = 1.0f / l_i[i];
        int s = q0 + ty * 4 + i;
        float4 o;
        o.x = acc[i][0] * inv_l;
        o.y = acc[i][1] * inv_l;
        o.z = acc[i][2] * inv_l;
        o.w = acc[i][3] * inv_l;
        *(float4*)&g_C[((size_t)b * SS + s) * DD + h * HD + tx * 4] = o;
    }
}

// ---------------------------------------------------------------------------
// Kernel 3: output projection  out = ctx @ Wp + bp
// Grid: x = 12 N-tiles, y = 256 M-tiles.
// ---------------------------------------------------------------------------
__global__ __launch_bounds__(256)
void proj_kernel(const float* __restrict__ Wp, const float* __restrict__ bp,
                 float* __restrict__ out) {
    int n0 = blockIdx.x * 64;
    int m0 = blockIdx.y * 64;
    int tid = threadIdx.x;
    int tx  = tid & 15, ty = tid >> 4;

    __shared__ float As[16][64];
    __shared__ float Bs[16][64];

    float acc[4][4] = {};

    int a_row = tid >> 2;
    int a_kv  = (tid & 3) * 4;
    int b_row = tid >> 4;
    int b_cv  = (tid & 15) * 4;

    for (int k0 = 0; k0 < DD; k0 += 16) {
        float4 av = *(const float4*)&g_C[(size_t)(m0 + a_row) * DD + k0 + a_kv];
        As[a_kv + 0][a_row] = av.x;
        As[a_kv + 1][a_row] = av.y;
        As[a_kv + 2][a_row] = av.z;
        As[a_kv + 3][a_row] = av.w;
        *(float4*)&Bs[b_row][b_cv] =
            *(const float4*)&Wp[(size_t)(k0 + b_row) * DD + n0 + b_cv];
        __syncthreads();
        #pragma unroll
        for (int k = 0; k < 16; k++) {
            float4 a = *(float4*)&As[k][ty * 4];
            float4 b = *(float4*)&Bs[k][tx * 4];
            float ar[4] = {a.x, a.y, a.z, a.w};
            float br[4] = {b.x, b.y, b.z, b.w};
            #pragma unroll
            for (int i = 0; i < 4; i++)
                #pragma unroll
                for (int j = 0; j < 4; j++)
                    acc[i][j] += ar[i] * br[j];
        }
        __syncthreads();
    }

    float4 b4 = *(const float4*)&bp[n0 + tx * 4];
    #pragma unroll
    for (int i = 0; i < 4; i++) {
        int m = m0 + ty * 4 + i;
        float4 o;
        o.x = acc[i][0] + b4.x;
        o.y = acc[i][1] + b4.y;
        o.z = acc[i][2] + b4.z;
        o.w = acc[i][3] + b4.w;
        *(float4*)&out[(size_t)m * DD + n0 + tx * 4] = o;
    }
}

// ---------------------------------------------------------------------------
extern "C" void kernel_launch(void* const* d_in, const int* in_sizes, int n_in,
                              void* d_out, int out_size) {
    const float* x  = (const float*)d_in[0];
    const float* Wq = (const float*)d_in[1];
    const float* bq = (const float*)d_in[2];
    const float* Wk = (const float*)d_in[3];
    const float* bk = (const float*)d_in[4];
    const float* Wv = (const float*)d_in[5];
    const float* bv = (const float*)d_in[6];
    const float* Wp = (const float*)d_in[7];
    const float* bp = (const float*)d_in[8];
    float* out = (float*)d_out;

    // QKV projections
    qkv_kernel<<<dim3(36, M_ROWS / 64), 256>>>(x, Wq, bq, Wk, bk, Wv, bv);

    // Flash attention
    size_t smem = (size_t)(3 * 64 * 64 + 64 * 65) * sizeof(float);  // 65,792 B
    cudaFuncSetAttribute(attn_kernel,
                         cudaFuncAttributeMaxDynamicSharedMemorySize, (int)smem);
    attn_kernel<<<dim3(SS / 64, BB * HH), 256, smem>>>();

    // Output projection
    proj_kernel<<<dim3(DD / 64, M_ROWS / 64), 256>>>(Wp, bp, out);
}

// round 2
// speedup vs baseline: 2.0011x; 2.0011x over previous
#include <cuda_runtime.h>
#include <math.h>

#define BB 8
#define SS 2048
#define DD 768
#define HH 12
#define HD 64
#define M_ROWS (BB*SS)

// Scratch (allocation-free: __device__ globals).
__device__ float g_Q[BB*HH*SS*HD];
__device__ float g_K[BB*HH*SS*HD];
__device__ float g_V[BB*HH*SS*HD];
__device__ float g_C[BB*SS*DD];

// ---------------------------------------------------------------------------
// helpers
// ---------------------------------------------------------------------------
__device__ __forceinline__ unsigned f2tf(float f) {
    unsigned u;
    asm("cvt.rna.tf32.f32 %0, %1;" : "=r"(u) : "f"(f));
    return u;
}

// D += A(16x8) * B(8x8), tf32 inputs, f32 accum.
__device__ __forceinline__ void mma8(float c[4], const unsigned a[4],
                                     unsigned b0, unsigned b1) {
    asm volatile(
        "mma.sync.aligned.m16n8k8.row.col.f32.tf32.tf32.f32 "
        "{%0,%1,%2,%3}, {%4,%5,%6,%7}, {%8,%9}, {%0,%1,%2,%3};"
        : "+f"(c[0]), "+f"(c[1]), "+f"(c[2]), "+f"(c[3])
        : "r"(a[0]), "r"(a[1]), "r"(a[2]), "r"(a[3]), "r"(b0), "r"(b1));
}

// k-dim pair-interleave within each aligned 8-group: pos(k)=(k%4)*2 + (k/4)%2.
// Makes fragment pairs (k, k+4) contiguous -> single LDS.64 per fragment pair.
// XOR swizzle by (row&3)<<3 spreads rows across banks.
__device__ __forceinline__ int swz32(int row, int k) {        // row width 32
    int pos = (k & 24) + (((k & 3) << 1) | ((k >> 2) & 1));
    return row * 32 + (pos ^ ((row & 3) << 3));
}
__device__ __forceinline__ int swz64(int row, int k) {        // row width 64
    int pos = (k & 56) + (((k & 3) << 1) | ((k >> 2) & 1));
    return row * 64 + (pos ^ ((row & 3) << 3));
}
// uint2 index of the fragment pair starting at even position p, row r, width W
__device__ __forceinline__ int fidx(int r, int p, int Wlog) {
    return ((r << Wlog) + (p ^ ((r & 3) << 3))) >> 1;
}

// ---------------------------------------------------------------------------
// Kernel 1: fused QKV projection via tf32 mma.
// Grid: x = 36 (mat*12+head), y = 128 (M tiles of 128). 256 thr = 8 warps.
// Block tile M=128 N=64 KC=32; warp tile 32x32.
// ---------------------------------------------------------------------------
__global__ __launch_bounds__(256, 2)
void qkv_kernel(const float* __restrict__ x,
                const float* __restrict__ Wq, const float* __restrict__ bq,
                const float* __restrict__ Wk, const float* __restrict__ bk,
                const float* __restrict__ Wv, const float* __restrict__ bv) {
    int nt  = blockIdx.x;
    int mat = nt / HH;
    int h   = nt % HH;
    const float* W    = (mat == 0) ? Wq : (mat == 1) ? Wk : Wv;
    const float* bias = (mat == 0) ? bq : (mat == 1) ? bk : bv;
    float*       Out  = (mat == 0) ? g_Q : (mat == 1) ? g_K : g_V;
    W    += h * DD * HD;
    bias += h * HD;

    int m0   = blockIdx.y * 128;
    int tid  = threadIdx.x;
    int warp = tid >> 5, lane = tid & 31;
    int g = lane >> 2, t4 = lane & 3;
    int wm = (warp >> 1) * 32;          // warp row offset (0,32,64,96)
    int wn = (warp & 1) * 32;           // warp col offset (0,32)

    __shared__ unsigned As[128 * 32];
    __shared__ unsigned Bs[64 * 32];
    const uint2* As2 = (const uint2*)As;
    const uint2* Bs2 = (const uint2*)Bs;

    float acc[2][4][4] = {};

    for (int k0 = 0; k0 < DD; k0 += 32) {
        // stage A: 128x32
        #pragma unroll
        for (int it = 0; it < 4; it++) {
            int idx = tid + it * 256;
            int m = idx >> 3, fv = idx & 7;
            int k = fv * 4;
            float4 v = *(const float4*)&x[(size_t)(m0 + m) * DD + k0 + k];
            As[swz32(m, k + 0)] = f2tf(v.x);
            As[swz32(m, k + 1)] = f2tf(v.y);
            As[swz32(m, k + 2)] = f2tf(v.z);
            As[swz32(m, k + 3)] = f2tf(v.w);
        }
        // stage B: 32x64 -> Bs[n][k]
        #pragma unroll
        for (int it = 0; it < 2; it++) {
            int idx = tid + it * 256;
            int k = idx >> 4, n4 = (idx & 15) * 4;
            float4 w = *(const float4*)&W[(size_t)(k0 + k) * HD + n4];
            Bs[swz32(n4 + 0, k)] = f2tf(w.x);
            Bs[swz32(n4 + 1, k)] = f2tf(w.y);
            Bs[swz32(n4 + 2, k)] = f2tf(w.z);
            Bs[swz32(n4 + 3, k)] = f2tf(w.w);
        }
        __syncthreads();

        #pragma unroll
        for (int kst = 0; kst < 4; kst++) {
            int pos = kst * 8 + 2 * t4;
            unsigned a[2][4];
            #pragma unroll
            for (int mt = 0; mt < 2; mt++) {
                int r = wm + mt * 16 + g;
                uint2 lo = As2[fidx(r, pos, 5)];
                uint2 hi = As2[fidx(r + 8, pos, 5)];
                a[mt][0] = lo.x; a[mt][1] = hi.x; a[mt][2] = lo.y; a[mt][3] = hi.y;
            }
            unsigned b[4][2];
            #pragma unroll
            for (int nb = 0; nb < 4; nb++) {
                int rb = wn + nb * 8 + g;
                uint2 bv = Bs2[fidx(rb, pos, 5)];
                b[nb][0] = bv.x; b[nb][1] = bv.y;
            }
            #pragma unroll
            for (int mt = 0; mt < 2; mt++)
                #pragma unroll
                for (int nb = 0; nb < 4; nb++)
                    mma8(acc[mt][nb], a[mt], b[nb][0], b[nb][1]);
        }
        __syncthreads();
    }

    int b_idx  = m0 / SS;
    int s_base = m0 % SS;
    #pragma unroll
    for (int mt = 0; mt < 2; mt++) {
        #pragma unroll
        for (int nb = 0; nb < 4; nb++) {
            int c = wn + nb * 8 + 2 * t4;
            float bx = bias[c], by = bias[c + 1];
            int s  = s_base + wm + mt * 16 + g;
            float2 o0 = {acc[mt][nb][0] + bx, acc[mt][nb][1] + by};
            float2 o1 = {acc[mt][nb][2] + bx, acc[mt][nb][3] + by};
            size_t base = (((size_t)b_idx * HH + h) * SS);
            *(float2*)&Out[(base + s) * HD + c]     = o0;
            *(float2*)&Out[(base + s + 8) * HD + c] = o1;
        }
    }
}

// ---------------------------------------------------------------------------
// Kernel 2: flash attention with tf32 mma. BR=128, BC=64.
// Grid: x = 16 q-tiles, y = 96 (b*H+h). 256 thr = 8 warps; warp w owns
// q-rows [16w, 16w+16) across the full 64-key strip -> softmax is
// quad-shuffle only; P strip is warp-private in smem.
// ---------------------------------------------------------------------------
__global__ __launch_bounds__(256, 2)
void attn_kernel() {
    int bh = blockIdx.y;
    int q0 = blockIdx.x * 128;
    const float* Qg = g_Q + (size_t)bh * SS * HD;
    const float* Kg = g_K + (size_t)bh * SS * HD;
    const float* Vg = g_V + (size_t)bh * SS * HD;
    int b = bh / HH, h = bh % HH;

    extern __shared__ unsigned sm[];
    unsigned* Ks = sm;            // [c][e]  64x64
    unsigned* Vs = sm + 4096;     // [e][c]  64x64
    unsigned* Ps = sm + 8192;     // [m][c]  128x64 (Q staging, then per-warp P)
    const uint2* Ks2 = (const uint2*)Ks;
    const uint2* Vs2 = (const uint2*)Vs;
    const uint2* Ps2 = (const uint2*)Ps;

    int tid = threadIdx.x;
    int warp = tid >> 5, lane = tid & 31;
    int g = lane >> 2, t4 = lane & 3;
    int wm = warp * 16;

    // Stage Q tile (128x64) into Ps region
    #pragma unroll
    for (int it = 0; it < 8; it++) {
        int idx = tid + it * 256;
        int m = idx >> 4, e4 = (idx & 15) * 4;
        float4 q = *(const float4*)&Qg[(size_t)(q0 + m) * HD + e4];
        Ps[swz64(m, e4 + 0)] = f2tf(q.x);
        Ps[swz64(m, e4 + 1)] = f2tf(q.y);
        Ps[swz64(m, e4 + 2)] = f2tf(q.z);
        Ps[swz64(m, e4 + 3)] = f2tf(q.w);
    }
    __syncthreads();

    // Q fragments in registers: 8 k-groups x 4 regs
    unsigned qa[8][4];
    #pragma unroll
    for (int grp = 0; grp < 8; grp++) {
        int pos = grp * 8 + 2 * t4;
        uint2 lo = Ps2[fidx(wm + g, pos, 6)];
        uint2 hi = Ps2[fidx(wm + g + 8, pos, 6)];
        qa[grp][0] = lo.x; qa[grp][1] = hi.x; qa[grp][2] = lo.y; qa[grp][3] = hi.y;
    }

    float o[8][4] = {};
    float m_i[2] = {-1e30f, -1e30f};
    float l_i[2] = {0.f, 0.f};
    const float inv_scale = 1.0f / (8.0f + 1e-6f);

    for (int kc0 = 0; kc0 < SS; kc0 += 64) {
        __syncthreads();
        // stage K chunk -> Ks[c][e], V chunk -> Vs[e][c]
        #pragma unroll
        for (int it = 0; it < 4; it++) {
            int idx = tid + it * 256;
            int c = idx >> 4, e4 = (idx & 15) * 4;
            float4 kv = *(const float4*)&Kg[(size_t)(kc0 + c) * HD + e4];
            Ks[swz64(c, e4 + 0)] = f2tf(kv.x);
            Ks[swz64(c, e4 + 1)] = f2tf(kv.y);
            Ks[swz64(c, e4 + 2)] = f2tf(kv.z);
            Ks[swz64(c, e4 + 3)] = f2tf(kv.w);
            float4 vv = *(const float4*)&Vg[(size_t)(kc0 + c) * HD + e4];
            Vs[swz64(e4 + 0, c)] = f2tf(vv.x);
            Vs[swz64(e4 + 1, c)] = f2tf(vv.y);
            Vs[swz64(e4 + 2, c)] = f2tf(vv.z);
            Vs[swz64(e4 + 3, c)] = f2tf(vv.w);
        }
        __syncthreads();

        // scores: sc[nt] covers key cols nt*8..nt*8+7
        float sc[8][4] = {};
        #pragma unroll
        for (int est = 0; est < 8; est++) {
            int pos = est * 8 + 2 * t4;
            #pragma unroll
            for (int ntl = 0; ntl < 8; ntl++) {
                int rn = ntl * 8 + g;
                uint2 bv = Ks2[fidx(rn, pos, 6)];
                mma8(sc[ntl], qa[est], bv.x, bv.y);
            }
        }

        // online softmax (rows g and g+8 of this warp's strip)
        float rmax0 = -1e30f, rmax1 = -1e30f;
        #pragma unroll
        for (int ntl = 0; ntl < 8; ntl++) {
            #pragma unroll
            for (int j = 0; j < 4; j++) sc[ntl][j] *= inv_scale;
            rmax0 = fmaxf(rmax0, fmaxf(sc[ntl][0], sc[ntl][1]));
            rmax1 = fmaxf(rmax1, fmaxf(sc[ntl][2], sc[ntl][3]));
        }
        #pragma unroll
        for (int off = 1; off <= 2; off <<= 1) {
            rmax0 = fmaxf(rmax0, __shfl_xor_sync(0xffffffffu, rmax0, off, 4));
            rmax1 = fmaxf(rmax1, __shfl_xor_sync(0xffffffffu, rmax1, off, 4));
        }
        float mn0 = fmaxf(m_i[0], rmax0);
        float mn1 = fmaxf(m_i[1], rmax1);
        float fac0 = __expf(m_i[0] - mn0);
        float fac1 = __expf(m_i[1] - mn1);
        m_i[0] = mn0; m_i[1] = mn1;

        float rs0 = 0.f, rs1 = 0.f;
        #pragma unroll
        for (int ntl = 0; ntl < 8; ntl++) {
            float p0 = __expf(sc[ntl][0] - mn0);
            float p1 = __expf(sc[ntl][1] - mn0);
            float p2 = __expf(sc[ntl][2] - mn1);
            float p3 = __expf(sc[ntl][3] - mn1);
            rs0 += p0 + p1; rs1 += p2 + p3;
            int c0 = ntl * 8 + 2 * t4;
            Ps[swz64(wm + g,     c0)]     = f2tf(p0);
            Ps[swz64(wm + g,     c0 + 1)] = f2tf(p1);
            Ps[swz64(wm + g + 8, c0)]     = f2tf(p2);
            Ps[swz64(wm + g + 8, c0 + 1)] = f2tf(p3);
        }
        #pragma unroll
        for (int off = 1; off <= 2; off <<= 1) {
            rs0 += __shfl_xor_sync(0xffffffffu, rs0, off, 4);
            rs1 += __shfl_xor_sync(0xffffffffu, rs1, off, 4);
        }
        l_i[0] = l_i[0] * fac0 + rs0;
        l_i[1] = l_i[1] * fac1 + rs1;
        #pragma unroll
        for (int et = 0; et < 8; et++) {
            o[et][0] *= fac0; o[et][1] *= fac0;
            o[et][2] *= fac1; o[et][3] *= fac1;
        }
        __syncwarp();

        // O += P @ V
        #pragma unroll
        for (int cst = 0; cst < 8; cst++) {
            int pos = cst * 8 + 2 * t4;
            uint2 lo = Ps2[fidx(wm + g, pos, 6)];
            uint2 hi = Ps2[fidx(wm + g + 8, pos, 6)];
            unsigned pa[4] = {lo.x, hi.x, lo.y, hi.y};
            #pragma unroll
            for (int et = 0; et < 8; et++) {
                int rv = et * 8 + g;
                uint2 bv = Vs2[fidx(rv, pos, 6)];
                mma8(o[et], pa, bv.x, bv.y);
            }
        }
        __syncwarp();   // P strip reads done before next iteration's writes
    }

    // normalize + store ctx in [B, S, H*HD]
    float il0 = 1.0f / l_i[0], il1 = 1.0f / l_i[1];
    int s0 = q0 + wm + g;
    #pragma unroll
    for (int et = 0; et < 8; et++) {
        int c = et * 8 + 2 * t4;
        float2 v0 = {o[et][0] * il0, o[et][1] * il0};
        float2 v1 = {o[et][2] * il1, o[et][3] * il1};
        *(float2*)&g_C[((size_t)b * SS + s0) * DD + h * HD + c]       = v0;
        *(float2*)&g_C[((size_t)b * SS + s0 + 8) * DD + h * HD + c]   = v1;
    }
}

// ---------------------------------------------------------------------------
// Kernel 3: output projection  out = ctx @ Wp + bp (tf32 mma)
// Grid: x = 12 N-tiles(64), y = 128 M-tiles(128).
// ---------------------------------------------------------------------------
__global__ __launch_bounds__(256, 2)
void proj_kernel(const float* __restrict__ Wp, const float* __restrict__ bp,
                 float* __restrict__ out) {
    int n0 = blockIdx.x * 64;
    int m0 = blockIdx.y * 128;
    int tid = threadIdx.x;
    int warp = tid >> 5, lane = tid & 31;
    int g = lane >> 2, t4 = lane & 3;
    int wm = (warp >> 1) * 32;
    int wn = (warp & 1) * 32;

    __shared__ unsigned As[128 * 32];
    __shared__ unsigned Bs[64 * 32];
    const uint2* As2 = (const uint2*)As;
    const uint2* Bs2 = (const uint2*)Bs;

    float acc[2][4][4] = {};

    for (int k0 = 0; k0 < DD; k0 += 32) {
        #pragma unroll
        for (int it = 0; it < 4; it++) {
            int idx = tid + it * 256;
            int m = idx >> 3, fv = idx & 7;
            int k = fv * 4;
            float4 v = *(const float4*)&g_C[(size_t)(m0 + m) * DD + k0 + k];
            As[swz32(m, k + 0)] = f2tf(v.x);
            As[swz32(m, k + 1)] = f2tf(v.y);
            As[swz32(m, k + 2)] = f2tf(v.z);
            As[swz32(m, k + 3)] = f2tf(v.w);
        }
        #pragma unroll
        for (int it = 0; it < 2; it++) {
            int idx = tid + it * 256;
            int k = idx >> 4, n4 = (idx & 15) * 4;
            float4 w = *(const float4*)&Wp[(size_t)(k0 + k) * DD + n0 + n4];
            Bs[swz32(n4 + 0, k)] = f2tf(w.x);
            Bs[swz32(n4 + 1, k)] = f2tf(w.y);
            Bs[swz32(n4 + 2, k)] = f2tf(w.z);
            Bs[swz32(n4 + 3, k)] = f2tf(w.w);
        }
        __syncthreads();

        #pragma unroll
        for (int kst = 0; kst < 4; kst++) {
            int pos = kst * 8 + 2 * t4;
            unsigned a[2][4];
            #pragma unroll
            for (int mt = 0; mt < 2; mt++) {
                int r = wm + mt * 16 + g;
                uint2 lo = As2[fidx(r, pos, 5)];
                uint2 hi = As2[fidx(r + 8, pos, 5)];
                a[mt][0] = lo.x; a[mt][1] = hi.x; a[mt][2] = lo.y; a[mt][3] = hi.y;
            }
            unsigned bfr[4][2];
            #pragma unroll
            for (int nb = 0; nb < 4; nb++) {
                int rb = wn + nb * 8 + g;
                uint2 bv = Bs2[fidx(rb, pos, 5)];
                bfr[nb][0] = bv.x; bfr[nb][1] = bv.y;
            }
            #pragma unroll
            for (int mt = 0; mt < 2; mt++)
                #pragma unroll
                for (int nb = 0; nb < 4; nb++)
                    mma8(acc[mt][nb], a[mt], bfr[nb][0], bfr[nb][1]);
        }
        __syncthreads();
    }

    #pragma unroll
    for (int mt = 0; mt < 2; mt++) {
        #pragma unroll
        for (int nb = 0; nb < 4; nb++) {
            int c = n0 + wn + nb * 8 + 2 * t4;
            float bx = bp[c], by = bp[c + 1];
            int m = m0 + wm + mt * 16 + g;
            float2 o0 = {acc[mt][nb][0] + bx, acc[mt][nb][1] + by};
            float2 o1 = {acc[mt][nb][2] + bx, acc[mt][nb][3] + by};
            *(float2*)&out[(size_t)m * DD + c]       = o0;
            *(float2*)&out[(size_t)(m + 8) * DD + c] = o1;
        }
    }
}

// ---------------------------------------------------------------------------
extern "C" void kernel_launch(void* const* d_in, const int* in_sizes, int n_in,
                              void* d_out, int out_size) {
    const float* x  = (const float*)d_in[0];
    const float* Wq = (const float*)d_in[1];
    const float* bq = (const float*)d_in[2];
    const float* Wk = (const float*)d_in[3];
    const float* bk = (const float*)d_in[4];
    const float* Wv = (const float*)d_in[5];
    const float* bv = (const float*)d_in[6];
    const float* Wp = (const float*)d_in[7];
    const float* bp = (const float*)d_in[8];
    float* out = (float*)d_out;

    qkv_kernel<<<dim3(36, M_ROWS / 128), 256>>>(x, Wq, bq, Wk, bk, Wv, bv);

    size_t smem = 16384 * sizeof(unsigned);   // 64 KB
    cudaFuncSetAttribute(attn_kernel,
                         cudaFuncAttributeMaxDynamicSharedMemorySize, (int)smem);
    attn_kernel<<<dim3(SS / 128, BB * HH), 256, smem>>>();

    proj_kernel<<<dim3(DD / 64, M_ROWS / 128), 256>>>(Wp, bp, out);
}

// round 8
// speedup vs baseline: 7.1761x; 3.5860x over previous
#include <cuda_runtime.h>
#include <cuda_fp16.h>
#include <math.h>
#include <stdint.h>

#define BB 8
#define SS 2048
#define DD 768
#define HH 12
#define HD 64
#define M_ROWS (BB*SS)

// fp16 scratch (allocation-free __device__ globals)
__device__ __half g_X [M_ROWS*DD];          // x as fp16 [m][k]
__device__ __half g_W [3*DD*DD];            // qkv weights, n-major: [mat*768 + h*64 + e][k]
__device__ __half g_Wp[DD*DD];              // Wp transposed: [n][k]
__device__ __half g_Q [BB*HH*SS*HD];
__device__ __half g_K [BB*HH*SS*HD];
__device__ __half g_V [BB*HH*SS*HD];
__device__ __half g_C [M_ROWS*DD];          // ctx fp16 [m][h*64+e]

// ---------------------------------------------------------------------------
// primitives
// ---------------------------------------------------------------------------
__device__ __forceinline__ uint32_t smem_u32(const void* p) {
    uint32_t a;
    asm("{ .reg .u64 t; cvta.to.shared.u64 t, %1; cvt.u32.u64 %0, t; }"
        : "=r"(a) : "l"(p));
    return a;
}
__device__ __forceinline__ void cp16(uint32_t dst, const void* src) {
    asm volatile("cp.async.cg.shared.global [%0], [%1], 16;" :: "r"(dst), "l"(src));
}
__device__ __forceinline__ void cp_commit() {
    asm volatile("cp.async.commit_group;" ::: "memory");
}
template<int N> __device__ __forceinline__ void cp_wait() {
    asm volatile("cp.async.wait_group %0;" :: "n"(N) : "memory");
}
__device__ __forceinline__ void ldsm4(uint32_t* r, uint32_t a) {
    asm volatile("ldmatrix.sync.aligned.m8n8.x4.shared.b16 {%0,%1,%2,%3}, [%4];"
        : "=r"(r[0]), "=r"(r[1]), "=r"(r[2]), "=r"(r[3]) : "r"(a));
}
__device__ __forceinline__ void ldsm4t(uint32_t* r, uint32_t a) {
    asm volatile("ldmatrix.sync.aligned.m8n8.x4.trans.shared.b16 {%0,%1,%2,%3}, [%4];"
        : "=r"(r[0]), "=r"(r[1]), "=r"(r[2]), "=r"(r[3]) : "r"(a));
}
__device__ __forceinline__ void mma16(float* c, const uint32_t* a,
                                      uint32_t b0, uint32_t b1) {
    asm volatile(
        "mma.sync.aligned.m16n8k16.row.col.f32.f16.f16.f32 "
        "{%0,%1,%2,%3},{%4,%5,%6,%7},{%8,%9},{%0,%1,%2,%3};"
        : "+f"(c[0]), "+f"(c[1]), "+f"(c[2]), "+f"(c[3])
        : "r"(a[0]), "r"(a[1]), "r"(a[2]), "r"(a[3]), "r"(b0), "r"(b1));
}
__device__ __forceinline__ uint32_t h2pack(float a, float b) {
    __half2 h = __floats2half2_rn(a, b);
    return *(uint32_t*)&h;
}

// ---------------------------------------------------------------------------
// prep kernels (fp32 -> fp16, weight transposes). One-time, ~40us total.
// ---------------------------------------------------------------------------
__global__ void prep_x(const float* __restrict__ x) {
    size_t idx = (size_t)blockIdx.x * 256 + threadIdx.x;   // one 8-elem slot
    const float4* s = (const float4*)x + idx * 2;
    float4 v0 = s[0], v1 = s[1];
    __half2 h0 = __floats2half2_rn(v0.x, v0.y);
    __half2 h1 = __floats2half2_rn(v0.z, v0.w);
    __half2 h2 = __floats2half2_rn(v1.x, v1.y);
    __half2 h3 = __floats2half2_rn(v1.z, v1.w);
    uint4 u;
    u.x = *(uint32_t*)&h0; u.y = *(uint32_t*)&h1;
    u.z = *(uint32_t*)&h2; u.w = *(uint32_t*)&h3;
    *(uint4*)&g_X[idx * 8] = u;
}

// [H][D][HD] -> n-major [mat*768 + h*64 + e][k]
__global__ void prep_w(const float* __restrict__ Wq, const float* __restrict__ Wk,
                       const float* __restrict__ Wv) {
    int mh = blockIdx.x;                   // 0..35
    int mat = mh / HH, h = mh % HH;
    const float* W = (mat == 0 ? Wq : mat == 1 ? Wk : Wv) + (size_t)h * DD * HD;
    __half* dst = g_W + ((size_t)mat * DD + h * HD) * DD;
    __shared__ float tile[32][HD + 1];
    int tid = threadIdx.x;
    for (int k0 = 0; k0 < DD; k0 += 32) {
        __syncthreads();
        #pragma unroll
        for (int it = 0; it < 8; it++) {
            int idx = tid + it * 256;
            int k = idx >> 6, e = idx & 63;
            tile[k][e] = W[(size_t)(k0 + k) * HD + e];
        }
        __syncthreads();
        #pragma unroll
        for (int it = 0; it < 8; it++) {
            int idx = tid + it * 256;
            int e = idx >> 5, k = idx & 31;
            dst[(size_t)e * DD + k0 + k] = __float2half(tile[k][e]);
        }
    }
}

// Wp [k][n] -> [n][k]
__global__ void prep_wp(const float* __restrict__ Wp) {
    int n0 = blockIdx.x * 32, k0 = blockIdx.y * 32;
    __shared__ float tile[32][33];
    int tid = threadIdx.x;
    #pragma unroll
    for (int it = 0; it < 4; it++) {
        int idx = tid + it * 256;
        int k = idx >> 5, n = idx & 31;
        tile[k][n] = Wp[(size_t)(k0 + k) * DD + n0 + n];
    }
    __syncthreads();
    #pragma unroll
    for (int it = 0; it < 4; it++) {
        int idx = tid + it * 256;
        int n = idx >> 5, k = idx & 31;
        g_Wp[(size_t)(n0 + n) * DD + k0 + k] = __float2half(tile[k][n]);
    }
}

// ---------------------------------------------------------------------------
// shared GEMM machinery: 128x128 block, 8 warps (2Mx4N) of 64x32,
// KC=32 double-buffered cp.async, row stride 40 halves (80B, conflict-free).
// ---------------------------------------------------------------------------
#define GSTRIDE 40

__device__ __forceinline__ void gemm_stage(uint32_t aB, uint32_t bB,
                                           const __half* Ag, const __half* Bg,
                                           int t, int tid) {
    #pragma unroll
    for (int it = 0; it < 2; it++) {
        int idx = tid + it * 256;
        int r = idx >> 2, s = idx & 3;
        cp16(aB + (r * GSTRIDE + s * 8) * 2, Ag + (size_t)r * DD + t * 32 + s * 8);
        cp16(bB + (r * GSTRIDE + s * 8) * 2, Bg + (size_t)r * DD + t * 32 + s * 8);
    }
    cp_commit();
}

__device__ __forceinline__ void gemm_compute(uint32_t aB, uint32_t bB,
                                             int lane, int wm, int wn,
                                             float acc[4][4][4]) {
    #pragma unroll
    for (int kst = 0; kst < 2; kst++) {
        uint32_t a[4][4], bf[4][2];
        #pragma unroll
        for (int mt = 0; mt < 4; mt++)
            ldsm4(a[mt], aB + ((wm + mt * 16 + (lane & 15)) * GSTRIDE
                               + kst * 16 + (lane >> 4) * 8) * 2);
        #pragma unroll
        for (int np = 0; np < 2; np++) {
            uint32_t r[4];
            ldsm4(r, bB + ((wn + np * 16 + (lane & 15)) * GSTRIDE
                           + kst * 16 + (lane >> 4) * 8) * 2);
            bf[np * 2][0] = r[0]; bf[np * 2][1] = r[2];
            bf[np * 2 + 1][0] = r[1]; bf[np * 2 + 1][1] = r[3];
        }
        #pragma unroll
        for (int mt = 0; mt < 4; mt++)
            #pragma unroll
            for (int nt = 0; nt < 4; nt++)
                mma16(acc[mt][nt], a[mt], bf[nt][0], bf[nt][1]);
    }
}

// ---------------------------------------------------------------------------
// Kernel 1: fused QKV GEMM. C[16384, 2304] = X @ Wn^T. Grid (18, 128).
// ---------------------------------------------------------------------------
__global__ __launch_bounds__(256, 2)
void qkv_hmma(const float* __restrict__ bq, const float* __restrict__ bk,
              const float* __restrict__ bv) {
    __shared__ __half Asm[2][128 * GSTRIDE];
    __shared__ __half Bsm[2][128 * GSTRIDE];
    int bx = blockIdx.x;
    int m0 = blockIdx.y * 128;
    int tid = threadIdx.x, warp = tid >> 5, lane = tid & 31;
    int g = lane >> 2, t4 = lane & 3;
    int wm = (warp >> 2) * 64, wn = (warp & 3) * 32;

    const __half* Ag = g_X + (size_t)m0 * DD;
    const __half* Bg = g_W + (size_t)bx * 128 * DD;
    uint32_t aB[2] = {smem_u32(Asm[0]), smem_u32(Asm[1])};
    uint32_t bB[2] = {smem_u32(Bsm[0]), smem_u32(Bsm[1])};

    float acc[4][4][4] = {};
    gemm_stage(aB[0], bB[0], Ag, Bg, 0, tid);
    for (int t = 0; t < 24; t++) {
        if (t < 23) { gemm_stage(aB[(t+1)&1], bB[(t+1)&1], Ag, Bg, t + 1, tid);
                      cp_wait<1>(); }
        else cp_wait<0>();
        __syncthreads();
        gemm_compute(aB[t & 1], bB[t & 1], lane, wm, wn, acc);
        __syncthreads();
    }

    int matIdx  = (bx * 128) / DD;
    int remBase = (bx * 128) % DD + wn;
    __half* Out = matIdx == 0 ? g_Q : matIdx == 1 ? g_K : g_V;
    const float* bias = matIdx == 0 ? bq : matIdx == 1 ? bk : bv;
    #pragma unroll
    for (int nt = 0; nt < 4; nt++) {
        int rem = remBase + nt * 8 + 2 * t4;
        int h = rem >> 6, e = rem & 63;
        float2 bb = *(const float2*)&bias[h * HD + e];
        #pragma unroll
        for (int mt = 0; mt < 4; mt++) {
            int m = m0 + wm + mt * 16 + g;
            int b = m >> 11, s = m & 2047;
            size_t base0 = (((size_t)b * HH + h) * SS + s) * HD + e;
            *(__half2*)&Out[base0] =
                __floats2half2_rn(acc[mt][nt][0] + bb.x, acc[mt][nt][1] + bb.y);
            *(__half2*)&Out[base0 + 8 * HD] =
                __floats2half2_rn(acc[mt][nt][2] + bb.x, acc[mt][nt][3] + bb.y);
        }
    }
}

// ---------------------------------------------------------------------------
// Kernel 3: output projection. out[16384, 768] = ctx @ Wp^T + bp. Grid (6, 128).
// ---------------------------------------------------------------------------
__global__ __launch_bounds__(256, 2)
void proj_hmma(const float* __restrict__ bp, float* __restrict__ out) {
    __shared__ __half Asm[2][128 * GSTRIDE];
    __shared__ __half Bsm[2][128 * GSTRIDE];
    int n0 = blockIdx.x * 128;
    int m0 = blockIdx.y * 128;
    int tid = threadIdx.x, warp = tid >> 5, lane = tid & 31;
    int g = lane >> 2, t4 = lane & 3;
    int wm = (warp >> 2) * 64, wn = (warp & 3) * 32;

    const __half* Ag = g_C + (size_t)m0 * DD;
    const __half* Bg = g_Wp + (size_t)n0 * DD;
    uint32_t aB[2] = {smem_u32(Asm[0]), smem_u32(Asm[1])};
    uint32_t bB[2] = {smem_u32(Bsm[0]), smem_u32(Bsm[1])};

    float acc[4][4][4] = {};
    gemm_stage(aB[0], bB[0], Ag, Bg, 0, tid);
    for (int t = 0; t < 24; t++) {
        if (t < 23) { gemm_stage(aB[(t+1)&1], bB[(t+1)&1], Ag, Bg, t + 1, tid);
                      cp_wait<1>(); }
        else cp_wait<0>();
        __syncthreads();
        gemm_compute(aB[t & 1], bB[t & 1], lane, wm, wn, acc);
        __syncthreads();
    }

    #pragma unroll
    for (int nt = 0; nt < 4; nt++) {
        int n = n0 + wn + nt * 8 + 2 * t4;
        float2 bb = *(const float2*)&bp[n];
        #pragma unroll
        for (int mt = 0; mt < 4; mt++) {
            int m = m0 + wm + mt * 16 + g;
            float2 o0 = {acc[mt][nt][0] + bb.x, acc[mt][nt][1] + bb.y};
            float2 o1 = {acc[mt][nt][2] + bb.x, acc[mt][nt][3] + bb.y};
            *(float2*)&out[(size_t)m * DD + n]       = o0;
            *(float2*)&out[(size_t)(m + 8) * DD + n] = o1;
        }
    }
}

// ---------------------------------------------------------------------------
// Kernel 2: flash attention, fp16 mma. BR=128, BC=64, 8 warps (16 rows each).
// Q register-resident; P repacked in registers (C-frag -> A-frag), no smem P.
// KV double-buffered via cp.async. Row stride 72 halves (144B, conflict-free).
// ---------------------------------------------------------------------------
#define ASTRIDE 72
#define KVSZ (64 * ASTRIDE)

__global__ __launch_bounds__(256, 2)
void attn_hmma() {
    extern __shared__ __half sh[];
    __half* Qs = sh;                    // 128 x 72
    __half* Ks = sh + 128 * ASTRIDE;    // 2 x 64 x 72
    __half* Vs = Ks + 2 * KVSZ;         // 2 x 64 x 72

    int bh = blockIdx.y, q0 = blockIdx.x * 128;
    const __half* Qg = g_Q + (size_t)bh * SS * HD;
    const __half* Kg = g_K + (size_t)bh * SS * HD;
    const __half* Vg = g_V + (size_t)bh * SS * HD;
    int b = bh / HH, h = bh % HH;

    int tid = threadIdx.x, warp = tid >> 5, lane = tid & 31;
    int g = lane >> 2, t4 = lane & 3;
    int wm = warp * 16;

    uint32_t qB = smem_u32(Qs), kB = smem_u32(Ks), vB = smem_u32(Vs);

    // stage Q (group 0)
    #pragma unroll
    for (int it = 0; it < 4; it++) {
        int idx = tid + it * 256;
        int r = idx >> 3, s = idx & 7;
        cp16(qB + (r * ASTRIDE + s * 8) * 2, Qg + (size_t)(q0 + r) * HD + s * 8);
    }
    cp_commit();

    #define STAGE_KV(kc, buf) do {                                              \
        const __half* Ksrc = Kg + (size_t)(kc) * 64 * HD;                       \
        const __half* Vsrc = Vg + (size_t)(kc) * 64 * HD;                       \
        uint32_t kd = kB + (buf) * KVSZ * 2, vd = vB + (buf) * KVSZ * 2;        \
        _Pragma("unroll")                                                       \
        for (int it = 0; it < 2; it++) {                                        \
            int idx = tid + it * 256;                                           \
            int r = idx >> 3, s = idx & 7;                                      \
            cp16(kd + (r * ASTRIDE + s * 8) * 2, Ksrc + (size_t)r * HD + s * 8);\
            cp16(vd + (r * ASTRIDE + s * 8) * 2, Vsrc + (size_t)r * HD + s * 8);\
        }                                                                       \
        cp_commit();                                                            \
    } while (0)

    STAGE_KV(0, 0);
    cp_wait<1>();            // Q done (KV0 may still be in flight)
    __syncthreads();

    // Q fragments: 4 k-steps x 4 regs, register-resident for all 32 chunks
    uint32_t qa[4][4];
    #pragma unroll
    for (int kst = 0; kst < 4; kst++)
        ldsm4(qa[kst], qB + ((wm + (lane & 15)) * ASTRIDE
                             + kst * 16 + (lane >> 4) * 8) * 2);

    float o[8][4] = {};
    float m_i[2] = {-1e30f, -1e30f};
    float l_i[2] = {0.f, 0.f};
    const float inv_scale = 1.0f / (8.0f + 1e-6f);   // 1/(sqrt(64)+EPS)

    for (int kc = 0; kc < 32; kc++) {
        if (kc < 31) { STAGE_KV(kc + 1, (kc + 1) & 1); cp_wait<1>(); }
        else cp_wait<0>();
        __syncthreads();
        uint32_t kb = kB + (kc & 1) * KVSZ * 2;
        uint32_t vb = vB + (kc & 1) * KVSZ * 2;

        // scores: 8 n8-tiles over 64 keys
        float sc[8][4] = {};
        #pragma unroll
        for (int kst = 0; kst < 4; kst++) {
            #pragma unroll
            for (int cp = 0; cp < 4; cp++) {
                uint32_t r[4];
                ldsm4(r, kb + ((cp * 16 + (lane & 15)) * ASTRIDE
                               + kst * 16 + (lane >> 4) * 8) * 2);
                mma16(sc[cp * 2],     qa[kst], r[0], r[2]);
                mma16(sc[cp * 2 + 1], qa[kst], r[1], r[3]);
            }
        }

        // online softmax (rows g and g+8; quad-shuffle reductions)
        float rmax0 = -1e30f, rmax1 = -1e30f;
        #pragma unroll
        for (int nt = 0; nt < 8; nt++) {
            #pragma unroll
            for (int j = 0; j < 4; j++) sc[nt][j] *= inv_scale;
            rmax0 = fmaxf(rmax0, fmaxf(sc[nt][0], sc[nt][1]));
            rmax1 = fmaxf(rmax1, fmaxf(sc[nt][2], sc[nt][3]));
        }
        #pragma unroll
        for (int off = 1; off <= 2; off <<= 1) {
            rmax0 = fmaxf(rmax0, __shfl_xor_sync(0xffffffffu, rmax0, off, 4));
            rmax1 = fmaxf(rmax1, __shfl_xor_sync(0xffffffffu, rmax1, off, 4));
        }
        float mn0 = fmaxf(m_i[0], rmax0);
        float mn1 = fmaxf(m_i[1], rmax1);
        float fac0 = __expf(m_i[0] - mn0);
        float fac1 = __expf(m_i[1] - mn1);
        m_i[0] = mn0; m_i[1] = mn1;

        float rs0 = 0.f, rs1 = 0.f;
        #pragma unroll
        for (int nt = 0; nt < 8; nt++) {
            sc[nt][0] = __expf(sc[nt][0] - mn0);
            sc[nt][1] = __expf(sc[nt][1] - mn0);
            sc[nt][2] = __expf(sc[nt][2] - mn1);
            sc[nt][3] = __expf(sc[nt][3] - mn1);
            rs0 += sc[nt][0] + sc[nt][1];
            rs1 += sc[nt][2] + sc[nt][3];
        }
        #pragma unroll
        for (int off = 1; off <= 2; off <<= 1) {
            rs0 += __shfl_xor_sync(0xffffffffu, rs0, off, 4);
            rs1 += __shfl_xor_sync(0xffffffffu, rs1, off, 4);
        }
        l_i[0] = l_i[0] * fac0 + rs0;
        l_i[1] = l_i[1] * fac1 + rs1;
        #pragma unroll
        for (int et = 0; et < 8; et++) {
            o[et][0] *= fac0; o[et][1] *= fac0;
            o[et][2] *= fac1; o[et][3] *= fac1;
        }

        // O += P @ V ; P repacked from score C-frags to A-frags in registers
        #pragma unroll
        for (int kst = 0; kst < 4; kst++) {
            uint32_t pa[4] = {
                h2pack(sc[2*kst][0],   sc[2*kst][1]),
                h2pack(sc[2*kst][2],   sc[2*kst][3]),
                h2pack(sc[2*kst+1][0], sc[2*kst+1][1]),
                h2pack(sc[2*kst+1][2], sc[2*kst+1][3])};
            #pragma unroll
            for (int eb = 0; eb < 4; eb++) {
                uint32_t r[4];
                ldsm4t(r, vb + ((kst * 16 + (lane & 15)) * ASTRIDE
                                + eb * 16 + (lane >> 4) * 8) * 2);
                mma16(o[eb * 2],     pa, r[0], r[1]);
                mma16(o[eb * 2 + 1], pa, r[2], r[3]);
            }
        }
        __syncthreads();   // buffer reads done before kc+2 staging overwrites
    }

    // normalize + store ctx fp16 into [m][768]
    float il0 = 1.0f / l_i[0], il1 = 1.0f / l_i[1];
    int s0 = q0 + wm + g;
    size_t row0 = ((size_t)b * SS + s0) * DD + h * HD;
    #pragma unroll
    for (int et = 0; et < 8; et++) {
        int c = et * 8 + 2 * t4;
        *(__half2*)&g_C[row0 + c] =
            __floats2half2_rn(o[et][0] * il0, o[et][1] * il0);
        *(__half2*)&g_C[row0 + 8 * DD + c] =
            __floats2half2_rn(o[et][2] * il1, o[et][3] * il1);
    }
}

// ---------------------------------------------------------------------------
extern "C" void kernel_launch(void* const* d_in, const int* in_sizes, int n_in,
                              void* d_out, int out_size) {
    const float* x  = (const float*)d_in[0];
    const float* Wq = (const float*)d_in[1];
    const float* bq = (const float*)d_in[2];
    const float* Wk = (const float*)d_in[3];
    const float* bk = (const float*)d_in[4];
    const float* Wv = (const float*)d_in[5];
    const float* bv = (const float*)d_in[6];
    const float* Wp = (const float*)d_in[7];
    const float* bp = (const float*)d_in[8];
    float* out = (float*)d_out;

    // one-time fp16 conversions / transposes
    prep_x<<<M_ROWS * DD / (8 * 256), 256>>>(x);
    prep_w<<<36, 256>>>(Wq, Wk, Wv);
    prep_wp<<<dim3(DD / 32, DD / 32), 256>>>(Wp);

    // fused QKV projection
    qkv_hmma<<<dim3(3 * DD / 128, M_ROWS / 128), 256>>>(bq, bk, bv);

    // flash attention
    size_t smem = (size_t)(128 * ASTRIDE + 4 * KVSZ) * sizeof(__half);  // 55296
    cudaFuncSetAttribute(attn_hmma, cudaFuncAttributeMaxDynamicSharedMemorySize,
                         (int)smem);
    attn_hmma<<<dim3(SS / 128, BB * HH), 256, smem>>>();

    // output projection
    proj_hmma<<<dim3(DD / 128, M_ROWS / 128), 256>>>(bp, out);
}

// round 9
// speedup vs baseline: 7.2286x; 1.0073x over previous
#include <cuda_runtime.h>
#include <cuda_fp16.h>
#include <math.h>
#include <stdint.h>

#define BB 8
#define SS 2048
#define DD 768
#define HH 12
#define HD 64
#define M_ROWS (BB*SS)

// fp16 scratch (allocation-free __device__ globals)
__device__ __half g_X [M_ROWS*DD];          // x as fp16 [m][k]
__device__ __half g_W [3*DD*DD];            // qkv weights, n-major
__device__ __half g_Wp[DD*DD];              // Wp transposed: [n][k]
__device__ __half g_Q [BB*HH*SS*HD];
__device__ __half g_K [BB*HH*SS*HD];
__device__ __half g_V [BB*HH*SS*HD];
__device__ __half g_C [M_ROWS*DD];          // ctx fp16 [m][h*64+e]

// ---------------------------------------------------------------------------
// primitives
// ---------------------------------------------------------------------------
__device__ __forceinline__ uint32_t smem_u32(const void* p) {
    uint32_t a;
    asm("{ .reg .u64 t; cvta.to.shared.u64 t, %1; cvt.u32.u64 %0, t; }"
        : "=r"(a) : "l"(p));
    return a;
}
__device__ __forceinline__ void cp16(uint32_t dst, const void* src) {
    asm volatile("cp.async.cg.shared.global [%0], [%1], 16;" :: "r"(dst), "l"(src));
}
__device__ __forceinline__ void cp_commit() {
    asm volatile("cp.async.commit_group;" ::: "memory");
}
template<int N> __device__ __forceinline__ void cp_wait() {
    asm volatile("cp.async.wait_group %0;" :: "n"(N) : "memory");
}
__device__ __forceinline__ void ldsm4(uint32_t* r, uint32_t a) {
    asm volatile("ldmatrix.sync.aligned.m8n8.x4.shared.b16 {%0,%1,%2,%3}, [%4];"
        : "=r"(r[0]), "=r"(r[1]), "=r"(r[2]), "=r"(r[3]) : "r"(a));
}
__device__ __forceinline__ void ldsm4t(uint32_t* r, uint32_t a) {
    asm volatile("ldmatrix.sync.aligned.m8n8.x4.trans.shared.b16 {%0,%1,%2,%3}, [%4];"
        : "=r"(r[0]), "=r"(r[1]), "=r"(r[2]), "=r"(r[3]) : "r"(a));
}
__device__ __forceinline__ void mma16(float* c, const uint32_t* a,
                                      uint32_t b0, uint32_t b1) {
    asm volatile(
        "mma.sync.aligned.m16n8k16.row.col.f32.f16.f16.f32 "
        "{%0,%1,%2,%3},{%4,%5,%6,%7},{%8,%9},{%0,%1,%2,%3};"
        : "+f"(c[0]), "+f"(c[1]), "+f"(c[2]), "+f"(c[3])
        : "r"(a[0]), "r"(a[1]), "r"(a[2]), "r"(a[3]), "r"(b0), "r"(b1));
}
__device__ __forceinline__ uint32_t h2pack(float a, float b) {
    __half2 h = __floats2half2_rn(a, b);
    return *(uint32_t*)&h;
}

// ---------------------------------------------------------------------------
// prep kernels (fp32 -> fp16, weight transposes)
// ---------------------------------------------------------------------------
__global__ void prep_x(const float* __restrict__ x) {
    size_t idx = (size_t)blockIdx.x * 256 + threadIdx.x;
    const float4* s = (const float4*)x + idx * 2;
    float4 v0 = s[0], v1 = s[1];
    __half2 h0 = __floats2half2_rn(v0.x, v0.y);
    __half2 h1 = __floats2half2_rn(v0.z, v0.w);
    __half2 h2 = __floats2half2_rn(v1.x, v1.y);
    __half2 h3 = __floats2half2_rn(v1.z, v1.w);
    uint4 u;
    u.x = *(uint32_t*)&h0; u.y = *(uint32_t*)&h1;
    u.z = *(uint32_t*)&h2; u.w = *(uint32_t*)&h3;
    *(uint4*)&g_X[idx * 8] = u;
}

__global__ void prep_w(const float* __restrict__ Wq, const float* __restrict__ Wk,
                       const float* __restrict__ Wv) {
    int mh = blockIdx.x;
    int mat = mh / HH, h = mh % HH;
    const float* W = (mat == 0 ? Wq : mat == 1 ? Wk : Wv) + (size_t)h * DD * HD;
    __half* dst = g_W + ((size_t)mat * DD + h * HD) * DD;
    __shared__ float tile[32][HD + 1];
    int tid = threadIdx.x;
    for (int k0 = 0; k0 < DD; k0 += 32) {
        __syncthreads();
        #pragma unroll
        for (int it = 0; it < 8; it++) {
            int idx = tid + it * 256;
            int k = idx >> 6, e = idx & 63;
            tile[k][e] = W[(size_t)(k0 + k) * HD + e];
        }
        __syncthreads();
        #pragma unroll
        for (int it = 0; it < 8; it++) {
            int idx = tid + it * 256;
            int e = idx >> 5, k = idx & 31;
            dst[(size_t)e * DD + k0 + k] = __float2half(tile[k][e]);
        }
    }
}

__global__ void prep_wp(const float* __restrict__ Wp) {
    int n0 = blockIdx.x * 32, k0 = blockIdx.y * 32;
    __shared__ float tile[32][33];
    int tid = threadIdx.x;
    #pragma unroll
    for (int it = 0; it < 4; it++) {
        int idx = tid + it * 256;
        int k = idx >> 5, n = idx & 31;
        tile[k][n] = Wp[(size_t)(k0 + k) * DD + n0 + n];
    }
    __syncthreads();
    #pragma unroll
    for (int it = 0; it < 4; it++) {
        int idx = tid + it * 256;
        int n = idx >> 5, k = idx & 31;
        g_Wp[(size_t)(n0 + n) * DD + k0 + k] = __float2half(tile[k][n]);
    }
}

// ---------------------------------------------------------------------------
// GEMM: 128x128 block, 8 warps (2Mx4N) of 64x32, KC=32,
// 4-stage cp.async ring, ONE __syncthreads per k-tile.
// Row stride 40 halves (80B, conflict-free ldmatrix/cp.async).
// ---------------------------------------------------------------------------
#define GSTRIDE 40
#define GTILE   (128 * GSTRIDE)           // halves per stage buffer
#define GSM_BYTES (8 * GTILE * 2)         // 4 stages x (A+B)

__device__ __forceinline__ void gemm_stage(uint32_t aB, uint32_t bB,
                                           const __half* Ag, const __half* Bg,
                                           int t, int tid) {
    #pragma unroll
    for (int it = 0; it < 2; it++) {
        int idx = tid + it * 256;
        int r = idx >> 2, s = idx & 3;
        cp16(aB + (r * GSTRIDE + s * 8) * 2, Ag + (size_t)r * DD + t * 32 + s * 8);
        cp16(bB + (r * GSTRIDE + s * 8) * 2, Bg + (size_t)r * DD + t * 32 + s * 8);
    }
}

__device__ __forceinline__ void gemm_compute(uint32_t aB, uint32_t bB,
                                             int lane, int wm, int wn,
                                             float acc[4][4][4]) {
    #pragma unroll
    for (int kst = 0; kst < 2; kst++) {
        uint32_t a[4][4], bf[4][2];
        #pragma unroll
        for (int mt = 0; mt < 4; mt++)
            ldsm4(a[mt], aB + ((wm + mt * 16 + (lane & 15)) * GSTRIDE
                               + kst * 16 + (lane >> 4) * 8) * 2);
        #pragma unroll
        for (int np = 0; np < 2; np++) {
            uint32_t r[4];
            ldsm4(r, bB + ((wn + np * 16 + (lane & 15)) * GSTRIDE
                           + kst * 16 + (lane >> 4) * 8) * 2);
            bf[np * 2][0] = r[0]; bf[np * 2][1] = r[2];
            bf[np * 2 + 1][0] = r[1]; bf[np * 2 + 1][1] = r[3];
        }
        #pragma unroll
        for (int mt = 0; mt < 4; mt++)
            #pragma unroll
            for (int nt = 0; nt < 4; nt++)
                mma16(acc[mt][nt], a[mt], bf[nt][0], bf[nt][1]);
    }
}

// Body shared by qkv/proj: multistage mainloop leaving result in acc.
#define GEMM_MAINLOOP(Ag, Bg)                                                  \
    uint32_t aS[4], bS[4];                                                     \
    {                                                                          \
        uint32_t base = smem_u32(dynsm);                                       \
        _Pragma("unroll")                                                      \
        for (int s = 0; s < 4; s++) {                                          \
            aS[s] = base + s * GTILE * 2;                                      \
            bS[s] = base + (4 + s) * GTILE * 2;                                \
        }                                                                      \
    }                                                                          \
    float acc[4][4][4] = {};                                                   \
    _Pragma("unroll")                                                          \
    for (int s = 0; s < 3; s++) {                                              \
        gemm_stage(aS[s], bS[s], Ag, Bg, s, tid);                              \
        cp_commit();                                                           \
    }                                                                          \
    for (int t = 0; t < 24; t++) {                                             \
        cp_wait<2>();                                                          \
        __syncthreads();                                                       \
        if (t + 3 < 24) gemm_stage(aS[(t+3)&3], bS[(t+3)&3], Ag, Bg, t+3, tid);\
        cp_commit();                                                           \
        gemm_compute(aS[t & 3], bS[t & 3], lane, wm, wn, acc);                 \
    }

// ---------------------------------------------------------------------------
// Kernel 1: fused QKV GEMM. C[16384, 2304] = X @ Wn^T. Grid (18, 128).
// ---------------------------------------------------------------------------
__global__ __launch_bounds__(256, 2)
void qkv_hmma(const float* __restrict__ bq, const float* __restrict__ bk,
              const float* __restrict__ bv) {
    extern __shared__ __half dynsm[];
    int bx = blockIdx.x;
    int m0 = blockIdx.y * 128;
    int tid = threadIdx.x, warp = tid >> 5, lane = tid & 31;
    int g = lane >> 2, t4 = lane & 3;
    int wm = (warp >> 2) * 64, wn = (warp & 3) * 32;

    const __half* Ag = g_X + (size_t)m0 * DD;
    const __half* Bg = g_W + (size_t)bx * 128 * DD;

    GEMM_MAINLOOP(Ag, Bg)

    int matIdx  = (bx * 128) / DD;
    int remBase = (bx * 128) % DD + wn;
    __half* Out = matIdx == 0 ? g_Q : matIdx == 1 ? g_K : g_V;
    const float* bias = matIdx == 0 ? bq : matIdx == 1 ? bk : bv;
    #pragma unroll
    for (int nt = 0; nt < 4; nt++) {
        int rem = remBase + nt * 8 + 2 * t4;
        int h = rem >> 6, e = rem & 63;
        float2 bb = *(const float2*)&bias[h * HD + e];
        #pragma unroll
        for (int mt = 0; mt < 4; mt++) {
            int m = m0 + wm + mt * 16 + g;
            int b = m >> 11, s = m & 2047;
            size_t base0 = (((size_t)b * HH + h) * SS + s) * HD + e;
            *(__half2*)&Out[base0] =
                __floats2half2_rn(acc[mt][nt][0] + bb.x, acc[mt][nt][1] + bb.y);
            *(__half2*)&Out[base0 + 8 * HD] =
                __floats2half2_rn(acc[mt][nt][2] + bb.x, acc[mt][nt][3] + bb.y);
        }
    }
}

// ---------------------------------------------------------------------------
// Kernel 3: output projection. out[16384, 768] = ctx @ Wp^T + bp. Grid (6, 128).
// ---------------------------------------------------------------------------
__global__ __launch_bounds__(256, 2)
void proj_hmma(const float* __restrict__ bp, float* __restrict__ out) {
    extern __shared__ __half dynsm[];
    int n0 = blockIdx.x * 128;
    int m0 = blockIdx.y * 128;
    int tid = threadIdx.x, warp = tid >> 5, lane = tid & 31;
    int g = lane >> 2, t4 = lane & 3;
    int wm = (warp >> 2) * 64, wn = (warp & 3) * 32;

    const __half* Ag = g_C + (size_t)m0 * DD;
    const __half* Bg = g_Wp + (size_t)n0 * DD;

    GEMM_MAINLOOP(Ag, Bg)

    #pragma unroll
    for (int nt = 0; nt < 4; nt++) {
        int n = n0 + wn + nt * 8 + 2 * t4;
        float2 bb = *(const float2*)&bp[n];
        #pragma unroll
        for (int mt = 0; mt < 4; mt++) {
            int m = m0 + wm + mt * 16 + g;
            float2 o0 = {acc[mt][nt][0] + bb.x, acc[mt][nt][1] + bb.y};
            float2 o1 = {acc[mt][nt][2] + bb.x, acc[mt][nt][3] + bb.y};
            *(float2*)&out[(size_t)m * DD + n]       = o0;
            *(float2*)&out[(size_t)(m + 8) * DD + n] = o1;
        }
    }
}

// ---------------------------------------------------------------------------
// Kernel 2: flash attention, fp16 mma. BR=128, BC=64, 8 warps (16 rows each).
// Q register-resident; P register-repacked. 3-stage KV ring via cp.async,
// ONE __syncthreads per chunk. Row stride 72 halves (144B, conflict-free).
// ---------------------------------------------------------------------------
#define ASTRIDE 72
#define KVSZ (64 * ASTRIDE)
#define ATT_SM_BYTES ((128 * ASTRIDE + 6 * KVSZ) * 2)

__global__ __launch_bounds__(256, 2)
void attn_hmma() {
    extern __shared__ __half sh[];
    __half* Qs = sh;                    // 128 x 72
    __half* Ks = sh + 128 * ASTRIDE;    // 3 x 64 x 72
    __half* Vs = Ks + 3 * KVSZ;         // 3 x 64 x 72

    int bh = blockIdx.y, q0 = blockIdx.x * 128;
    const __half* Qg = g_Q + (size_t)bh * SS * HD;
    const __half* Kg = g_K + (size_t)bh * SS * HD;
    const __half* Vg = g_V + (size_t)bh * SS * HD;
    int b = bh / HH, h = bh % HH;

    int tid = threadIdx.x, warp = tid >> 5, lane = tid & 31;
    int g = lane >> 2, t4 = lane & 3;
    int wm = warp * 16;

    uint32_t qB = smem_u32(Qs), kB = smem_u32(Ks), vB = smem_u32(Vs);

    // group 0: Q
    #pragma unroll
    for (int it = 0; it < 4; it++) {
        int idx = tid + it * 256;
        int r = idx >> 3, s = idx & 7;
        cp16(qB + (r * ASTRIDE + s * 8) * 2, Qg + (size_t)(q0 + r) * HD + s * 8);
    }
    cp_commit();

    #define STAGE_KV(kc, buf) do {                                              \
        const __half* Ksrc = Kg + (size_t)(kc) * 64 * HD;                       \
        const __half* Vsrc = Vg + (size_t)(kc) * 64 * HD;                       \
        uint32_t kd = kB + (buf) * KVSZ * 2, vd = vB + (buf) * KVSZ * 2;        \
        _Pragma("unroll")                                                       \
        for (int it = 0; it < 2; it++) {                                        \
            int idx = tid + it * 256;                                           \
            int r = idx >> 3, s = idx & 7;                                      \
            cp16(kd + (r * ASTRIDE + s * 8) * 2, Ksrc + (size_t)r * HD + s * 8);\
            cp16(vd + (r * ASTRIDE + s * 8) * 2, Vsrc + (size_t)r * HD + s * 8);\
        }                                                                       \
        cp_commit();                                                            \
    } while (0)

    STAGE_KV(0, 0);     // group 1
    STAGE_KV(1, 1);     // group 2

    cp_wait<2>();       // group 0 (Q) complete
    __syncthreads();

    uint32_t qa[4][4];
    #pragma unroll
    for (int kst = 0; kst < 4; kst++)
        ldsm4(qa[kst], qB + ((wm + (lane & 15)) * ASTRIDE
                             + kst * 16 + (lane >> 4) * 8) * 2);

    float o[8][4] = {};
    float m_i[2] = {-1e30f, -1e30f};
    float l_i[2] = {0.f, 0.f};
    const float inv_scale = 1.0f / (8.0f + 1e-6f);   // 1/(sqrt(64)+EPS)

    for (int kc = 0; kc < 32; kc++) {
        cp_wait<1>();        // KV(kc) complete
        __syncthreads();
        if (kc + 2 < 32) STAGE_KV(kc + 2, (kc + 2) % 3);
        else cp_commit();    // keep group accounting uniform

        int bf = kc % 3;
        uint32_t kb = kB + bf * KVSZ * 2;
        uint32_t vb = vB + bf * KVSZ * 2;

        // scores: 8 n8-tiles over 64 keys
        float sc[8][4] = {};
        #pragma unroll
        for (int kst = 0; kst < 4; kst++) {
            #pragma unroll
            for (int cp = 0; cp < 4; cp++) {
                uint32_t r[4];
                ldsm4(r, kb + ((cp * 16 + (lane & 15)) * ASTRIDE
                               + kst * 16 + (lane >> 4) * 8) * 2);
                mma16(sc[cp * 2],     qa[kst], r[0], r[2]);
                mma16(sc[cp * 2 + 1], qa[kst], r[1], r[3]);
            }
        }

        // online softmax (rows g and g+8; quad-shuffle reductions)
        float rmax0 = -1e30f, rmax1 = -1e30f;
        #pragma unroll
        for (int nt = 0; nt < 8; nt++) {
            #pragma unroll
            for (int j = 0; j < 4; j++) sc[nt][j] *= inv_scale;
            rmax0 = fmaxf(rmax0, fmaxf(sc[nt][0], sc[nt][1]));
            rmax1 = fmaxf(rmax1, fmaxf(sc[nt][2], sc[nt][3]));
        }
        #pragma unroll
        for (int off = 1; off <= 2; off <<= 1) {
            rmax0 = fmaxf(rmax0, __shfl_xor_sync(0xffffffffu, rmax0, off, 4));
            rmax1 = fmaxf(rmax1, __shfl_xor_sync(0xffffffffu, rmax1, off, 4));
        }
        float mn0 = fmaxf(m_i[0], rmax0);
        float mn1 = fmaxf(m_i[1], rmax1);
        float fac0 = __expf(m_i[0] - mn0);
        float fac1 = __expf(m_i[1] - mn1);
        m_i[0] = mn0; m_i[1] = mn1;

        float rs0 = 0.f, rs1 = 0.f;
        #pragma unroll
        for (int nt = 0; nt < 8; nt++) {
            sc[nt][0] = __expf(sc[nt][0] - mn0);
            sc[nt][1] = __expf(sc[nt][1] - mn0);
            sc[nt][2] = __expf(sc[nt][2] - mn1);
            sc[nt][3] = __expf(sc[nt][3] - mn1);
            rs0 += sc[nt][0] + sc[nt][1];
            rs1 += sc[nt][2] + sc[nt][3];
        }
        #pragma unroll
        for (int off = 1; off <= 2; off <<= 1) {
            rs0 += __shfl_xor_sync(0xffffffffu, rs0, off, 4);
            rs1 += __shfl_xor_sync(0xffffffffu, rs1, off, 4);
        }
        l_i[0] = l_i[0] * fac0 + rs0;
        l_i[1] = l_i[1] * fac1 + rs1;
        #pragma unroll
        for (int et = 0; et < 8; et++) {
            o[et][0] *= fac0; o[et][1] *= fac0;
            o[et][2] *= fac1; o[et][3] *= fac1;
        }

        // O += P @ V ; P repacked from score C-frags to A-frags in registers
        #pragma unroll
        for (int kst = 0; kst < 4; kst++) {
            uint32_t pa[4] = {
                h2pack(sc[2*kst][0],   sc[2*kst][1]),
                h2pack(sc[2*kst][2],   sc[2*kst][3]),
                h2pack(sc[2*kst+1][0], sc[2*kst+1][1]),
                h2pack(sc[2*kst+1][2], sc[2*kst+1][3])};
            #pragma unroll
            for (int eb = 0; eb < 4; eb++) {
                uint32_t r[4];
                ldsm4t(r, vb + ((kst * 16 + (lane & 15)) * ASTRIDE
                                + eb * 16 + (lane >> 4) * 8) * 2);
                mma16(o[eb * 2],     pa, r[0], r[1]);
                mma16(o[eb * 2 + 1], pa, r[2], r[3]);
            }
        }
    }

    // normalize + store ctx fp16 into [m][768]
    float il0 = 1.0f / l_i[0], il1 = 1.0f / l_i[1];
    int s0 = q0 + wm + g;
    size_t row0 = ((size_t)b * SS + s0) * DD + h * HD;
    #pragma unroll
    for (int et = 0; et < 8; et++) {
        int c = et * 8 + 2 * t4;
        *(__half2*)&g_C[row0 + c] =
            __floats2half2_rn(o[et][0] * il0, o[et][1] * il0);
        *(__half2*)&g_C[row0 + 8 * DD + c] =
            __floats2half2_rn(o[et][2] * il1, o[et][3] * il1);
    }
}

// ---------------------------------------------------------------------------
extern "C" void kernel_launch(void* const* d_in, const int* in_sizes, int n_in,
                              void* d_out, int out_size) {
    const float* x  = (const float*)d_in[0];
    const float* Wq = (const float*)d_in[1];
    const float* bq = (const float*)d_in[2];
    const float* Wk = (const float*)d_in[3];
    const float* bk = (const float*)d_in[4];
    const float* Wv = (const float*)d_in[5];
    const float* bv = (const float*)d_in[6];
    const float* Wp = (const float*)d_in[7];
    const float* bp = (const float*)d_in[8];
    float* out = (float*)d_out;

    prep_x<<<M_ROWS * DD / (8 * 256), 256>>>(x);
    prep_w<<<36, 256>>>(Wq, Wk, Wv);
    prep_wp<<<dim3(DD / 32, DD / 32), 256>>>(Wp);

    cudaFuncSetAttribute(qkv_hmma, cudaFuncAttributeMaxDynamicSharedMemorySize,
                         GSM_BYTES);
    qkv_hmma<<<dim3(3 * DD / 128, M_ROWS / 128), 256, GSM_BYTES>>>(bq, bk, bv);

    cudaFuncSetAttribute(attn_hmma, cudaFuncAttributeMaxDynamicSharedMemorySize,
                         ATT_SM_BYTES);
    attn_hmma<<<dim3(SS / 128, BB * HH), 256, ATT_SM_BYTES>>>();

    cudaFuncSetAttribute(proj_hmma, cudaFuncAttributeMaxDynamicSharedMemorySize,
                         GSM_BYTES);
    proj_hmma<<<dim3(DD / 128, M_ROWS / 128), 256, GSM_BYTES>>>(bp, out);
}